// round 16
// baseline (speedup 1.0000x reference)
#include <cuda_runtime.h>
#include <math.h>

#define BATCH 64
#define TSTEPS 512
#define UNITS 1024
#define FIN 128
#define NCLS 16
#define NCTA 128
#define NTHR 512
#define KA 1152
#define KB 2048

typedef unsigned long long ull;

// ------------- static device scratch -------------
__device__ __align__(16) float d_Wa[NCTA * KA * 32];
__device__ __align__(16) float d_Wb[NCTA * KB * 32];   // [W1*g0 ; U1]
__device__ float d_b0r[4096];
__device__ float d_b1r[4096];   // b1 + W1^T be0
__device__ float d_cs[4096];    // colsum(W1*g0)
__device__ __align__(16) float d_Wfcg[UNITS * NCLS];   // g1-scaled Wfc
__device__ float d_csf[NCLS];   // colsum(g1*Wfc)
__device__ float d_bfcp[NCLS];  // bfc + Wfc^T be1
__device__ __align__(16) float d_h0[2][UNITS * BATCH];
__device__ __align__(16) float d_h1[2][UNITS * BATCH];
__device__ __align__(16) float d_h1T[BATCH * UNITS];   // [b][u] for phase C
__device__ __align__(16) float d_c0[UNITS * BATCH];
__device__ __align__(16) float d_c1[UNITS * BATCH];
__device__ float d_sum0[BATCH * NCTA];
__device__ float d_ssq0[BATCH * NCTA];
__device__ float d_sum1[BATCH * NCTA];
__device__ float d_ssq1[BATCH * NCTA];
__device__ __align__(16) float d_xT[2][FIN * BATCH];
__device__ unsigned d_flags[NCTA];

// ------------------------------ prep kernel ------------------------------
__global__ void prep_kernel(const float* __restrict__ in,
                            const float* __restrict__ W0, const float* __restrict__ U0,
                            const float* __restrict__ b0,
                            const float* __restrict__ g0, const float* __restrict__ be0,
                            const float* __restrict__ W1, const float* __restrict__ U1,
                            const float* __restrict__ b1,
                            const float* __restrict__ g1, const float* __restrict__ be1,
                            const float* __restrict__ Wfc, const float* __restrict__ bfc) {
    const long long N0 = (long long)NCTA * KA * 32;
    const long long N1 = (long long)NCTA * KB * 32;
    const long long O2 = N0 + N1;          // b0r (4096)
    const long long O2b = O2 + 4096;       // b1r+cs fold (4096, one pass writes both)
    const long long O3 = O2b + 4096;       // Wfcg (16384)   [BUGFIX: was O2b+8192 -> OOB writes]
    const long long O4 = O3 + 16384;       // csf/bfcp (32)
    const long long O5 = O4 + 32;          // zero region (262144)
    const long long O6 = O5 + 262144;      // xT (8192)
    const long long O7 = O6 + 8192;        // flags (NCTA)
    const long long TOTAL = O7 + NCTA;
    for (long long idx = (long long)blockIdx.x * blockDim.x + threadIdx.x;
         idx < TOTAL; idx += (long long)gridDim.x * blockDim.x) {
        if (idx < N0) {
            int cta = (int)(idx / (KA * 32));
            int r   = (int)(idx % (KA * 32));
            int k = r >> 5, col = r & 31;
            int gc = (col & 3) * 1024 + cta * 8 + (col >> 2);
            d_Wa[idx] = (k < 1024) ? U0[(long long)k * 4096 + gc]
                                   : W0[(long long)(k - 1024) * 4096 + gc];
        } else if (idx < O2) {
            long long j = idx - N0;
            int cta = (int)(j / (KB * 32));
            int r   = (int)(j % (KB * 32));
            int k = r >> 5, col = r & 31;
            int gc = (col & 3) * 1024 + cta * 8 + (col >> 2);
            d_Wb[j] = (k < 1024) ? W1[(long long)k * 4096 + gc] * g0[k]
                                 : U1[(long long)(k - 1024) * 4096 + gc];
        } else if (idx < O2b) {
            int j = (int)(idx - O2);
            int gc = ((j & 31) & 3) * 1024 + (j >> 5) * 8 + ((j & 31) >> 2);
            d_b0r[j] = b0[gc];
        } else if (idx < O3) {
            int j = (int)(idx - O2b);   // 0..4095: one pass fills BOTH b1r and cs
            int gc = ((j & 31) & 3) * 1024 + (j >> 5) * 8 + ((j & 31) >> 2);
            float sbe = 0.f, sg = 0.f;
            for (int k = 0; k < 1024; k++) {
                float w = W1[(long long)k * 4096 + gc];
                sbe += w * be0[k];
                sg  += w * g0[k];
            }
            d_b1r[j] = b1[gc] + sbe;
            d_cs[j]  = sg;
        } else if (idx < O4) {
            int j = (int)(idx - O3);
            d_Wfcg[j] = g1[j >> 4] * Wfc[j];
        } else if (idx < O5) {
            int j = (int)(idx - O4);
            if (j < 16) {
                float s = 0.f;
                for (int u = 0; u < 1024; u++) s += g1[u] * Wfc[u * 16 + j];
                d_csf[j] = s;
            } else {
                int c = j - 16;
                float s = 0.f;
                for (int u = 0; u < 1024; u++) s += be1[u] * Wfc[u * 16 + c];
                d_bfcp[c] = bfc[c] + s;
            }
        } else if (idx < O6) {
            int j = (int)(idx - O5);
            if (j < 65536)        d_c0[j] = 0.f;
            else if (j < 131072)  d_c1[j - 65536] = 0.f;
            else if (j < 196608)  d_h0[0][j - 131072] = 0.f;
            else                  d_h1[0][j - 196608] = 0.f;
        } else if (idx < O7) {
            int j = (int)(idx - O6);
            int f = j >> 6, b = j & 63;
            d_xT[0][j] = in[(long long)b * TSTEPS * FIN + f];
        } else {
            d_flags[(int)(idx - O7)] = 0u;
        }
    }
}

// ------------------------------ grid barrier ------------------------------
__device__ __forceinline__ void gridbar(unsigned& genc) {
    unsigned target = ++genc;
    __syncthreads();
    if (threadIdx.x == 0) {
        __threadfence();
        __stcg(&d_flags[blockIdx.x], target);
    }
    if (threadIdx.x < NCTA) {
        while (__ldcg(&d_flags[threadIdx.x]) < target) __nanosleep(32);
        __threadfence();
    }
    __syncthreads();
}

__device__ __forceinline__ float sigf(float z) { return 1.f / (1.f + expf(-z)); }

// ------------------------------ f32x2 helpers ------------------------------
__device__ __forceinline__ void ffma2(ull& d, ull a, ull b) {
    asm("fma.rn.f32x2 %0, %1, %2, %0;" : "+l"(d) : "l"(a), "l"(b));
}
__device__ __forceinline__ ull splat2(float w) {
    ull r; asm("mov.b64 %0, {%1, %1};" : "=l"(r) : "f"(w)); return r;
}
__device__ __forceinline__ float2 unpk(ull v) {
    float2 f; asm("mov.b64 {%0, %1}, %2;" : "=f"(f.x), "=f"(f.y) : "l"(v)); return f;
}
__device__ __forceinline__ void cpa16(void* dst, const void* src) {
    unsigned d = (unsigned)__cvta_generic_to_shared(dst);
    asm volatile("cp.async.cg.shared.global [%0], [%1], 16;" :: "r"(d), "l"(src));
}
__device__ __forceinline__ void cpa_commit() { asm volatile("cp.async.commit_group;"); }
__device__ __forceinline__ void cpa_wait1()  { asm volatile("cp.async.wait_group 1;"); }

// ---------------- pipelined tiled GEMM, 4-way K-split, partials to P -------
// Leaves partials in P = smemf[0 .. 8320), layout [sp*32+col]*65 + b.
// PH==1 additionally computes LN0 stats (SRS/SM2) behind the pipeline.
template<int PH>
__device__ __forceinline__ void gemm_block(
    float* __restrict__ smemf,
    const float4* __restrict__ srcA, const float4* __restrict__ srcB,
    const float* __restrict__ Wc, int tid,
    float* __restrict__ SRS, float* __restrict__ SM2)
{
    const int sp = tid >> 7, stid = tid & 127;
    const int cg = stid & 15, bg = stid >> 4;
    const int c0 = cg * 2, b0 = bg * 8;
    const int KSP = (PH == 0) ? 288 : 512;
    const int NT  = (PH == 0) ? 9 : 16;
    float* BUF = smemf + sp * 9216;
    ull A0[4] = {0,0,0,0}, A1[4] = {0,0,0,0};

    auto stage = [&](int ttp) {
        if (ttp < NT) {
            float* H = BUF + (ttp % 3) * 3072;
            float* W = H + 2048;
            const int kb = sp * KSP + ttp * 32;
            #pragma unroll
            for (int jj = 0; jj < 4; jj++) {
                int j = stid + jj * 128;
                int k = j >> 4, q = j & 15;
                int gk = kb + k;
                const float4* s = (gk < 1024) ? (srcA + gk * 16 + q)
                                              : (srcB + (gk - 1024) * 16 + q);
                cpa16(&H[k * 64 + q * 4], s);
            }
            #pragma unroll
            for (int jj = 0; jj < 2; jj++) {
                int j = stid + jj * 128;
                cpa16(&W[j * 4], &Wc[(size_t)kb * 32 + j * 4]);
            }
        }
        cpa_commit();
    };

    stage(0);
    stage(1);
    if (PH == 1 && tid < 64) {   // LN0 stats hidden behind the pipeline
        float s = 0.f, q = 0.f;
        for (int i = 0; i < NCTA; i++) {
            s += __ldcg(&d_sum0[tid * NCTA + i]);
            q += __ldcg(&d_ssq0[tid * NCTA + i]);
        }
        float mu = s * (1.f / 1024.f);
        float var = q * (1.f / 1024.f) - mu * mu;
        float rs = rsqrtf(var + 1e-3f);
        SRS[tid] = rs; SM2[tid] = mu * rs;
    }
    #pragma unroll 1
    for (int tt = 0; tt < NT; tt++) {
        cpa_wait1();
        __syncthreads();
        const float* H = BUF + (tt % 3) * 3072;
        const float* W = H + 2048;
        #pragma unroll 8
        for (int k = 0; k < 32; k++) {
            ulonglong2 p = *(const ulonglong2*)&H[k * 64 + b0];
            ulonglong2 r = *(const ulonglong2*)&H[k * 64 + b0 + 4];
            float2 wv = *(const float2*)&W[k * 32 + c0];
            ull w0 = splat2(wv.x), w1 = splat2(wv.y);
            ffma2(A0[0], p.x, w0); ffma2(A0[1], p.y, w0);
            ffma2(A0[2], r.x, w0); ffma2(A0[3], r.y, w0);
            ffma2(A1[0], p.x, w1); ffma2(A1[1], p.y, w1);
            ffma2(A1[2], r.x, w1); ffma2(A1[3], r.y, w1);
        }
        stage(tt + 2);
    }
    __syncthreads();
    // dump partials (stride-65 rows: conflict-free reads in cell update)
    float* P = smemf;
    {
        int base0 = (sp * 32 + c0) * 65 + b0;
        int base1 = (sp * 32 + c0 + 1) * 65 + b0;
        #pragma unroll
        for (int j = 0; j < 4; j++) {
            float2 v0 = unpk(A0[j]);
            P[base0 + 2 * j] = v0.x; P[base0 + 2 * j + 1] = v0.y;
            float2 v1 = unpk(A1[j]);
            P[base1 + 2 * j] = v1.x; P[base1 + 2 * j + 1] = v1.y;
        }
    }
    __syncthreads();
}

// ---------------------------- persistent kernel ----------------------------
extern __shared__ float smemf[];   // 37376 floats = 149504 B

__global__ void __launch_bounds__(NTHR, 1)
lstm_persist(const float* __restrict__ in, float* __restrict__ out) {
    __shared__ float SRS[64], SM2[64];
    __shared__ float LR[256];
    __shared__ float LG[16];
    __shared__ float CMU[2];

    const int tid = threadIdx.x;
    const int cta = blockIdx.x;
    unsigned genc = 0;
    float* P  = smemf;
    float* HN = smemf + 36864;  // 512 floats

    for (int t = 0; t < TSTEPS; t++) {
        const int cur = t & 1, nxt = cur ^ 1;

        // ================= Phase A : layer 0 =================
        gemm_block<0>(smemf, (const float4*)d_h0[cur], (const float4*)d_xT[cur],
                      d_Wa + (size_t)cta * KA * 32, tid, SRS, SM2);
        {
            int ul = tid >> 6, b = tid & 63;
            float z[4];
            #pragma unroll
            for (int g = 0; g < 4; g++) {
                int col = ul * 4 + g;
                float p0 = P[col * 65 + b];
                float p1 = P[(32 + col) * 65 + b];
                float p2 = P[(64 + col) * 65 + b];
                float p3 = P[(96 + col) * 65 + b];
                z[g] = ((p0 + p1) + p2) + p3 + __ldg(&d_b0r[cta * 32 + col]);
            }
            int gidx = (cta * 8 + ul) * 64 + b;
            float cn = sigf(z[1]) * d_c0[gidx] + sigf(z[0]) * tanhf(z[2]);
            d_c0[gidx] = cn;
            float hn = sigf(z[3]) * tanhf(cn);
            __stcg(&d_h0[nxt][gidx], hn);
            HN[tid] = hn;
        }
        __syncthreads();
        if (tid < 64) {
            float s = 0, q = 0;
            #pragma unroll
            for (int u = 0; u < 8; u++) { float v = HN[u * 64 + tid]; s += v; q += v * v; }
            __stcg(&d_sum0[tid * NCTA + cta], s);
            __stcg(&d_ssq0[tid * NCTA + cta], q);
        }
        if (t + 1 < TSTEPS && tid < 64) {
            __stcg(&d_xT[nxt][cta * 64 + tid],
                   __ldg(&in[(size_t)tid * TSTEPS * FIN + (size_t)(t + 1) * FIN + cta]));
        }
        gridbar(genc);

        // ================= Phase B : layer 1 (LN folded) =================
        gemm_block<1>(smemf, (const float4*)d_h0[nxt], (const float4*)d_h1[cur],
                      d_Wb + (size_t)cta * KB * 32, tid, SRS, SM2);
        {
            int ul = tid >> 6, b = tid & 63;
            float rs = SRS[b], m2 = SM2[b];
            float z[4];
            #pragma unroll
            for (int g = 0; g < 4; g++) {
                int col = ul * 4 + g;
                float p0 = P[col * 65 + b];
                float p1 = P[(32 + col) * 65 + b];
                float p2 = P[(64 + col) * 65 + b];
                float p3 = P[(96 + col) * 65 + b];
                z[g] = rs * (p0 + p1) + (p2 + p3)
                     - m2 * __ldg(&d_cs[cta * 32 + col]) + __ldg(&d_b1r[cta * 32 + col]);
            }
            int gidx = (cta * 8 + ul) * 64 + b;
            float cn = sigf(z[1]) * d_c1[gidx] + sigf(z[0]) * tanhf(z[2]);
            d_c1[gidx] = cn;
            float hn = sigf(z[3]) * tanhf(cn);
            __stcg(&d_h1[nxt][gidx], hn);
            __stcg(&d_h1T[b * UNITS + cta * 8 + ul], hn);
            HN[tid] = hn;
        }
        __syncthreads();
        if (tid < 64) {
            float s = 0, q = 0;
            #pragma unroll
            for (int u = 0; u < 8; u++) { float v = HN[u * 64 + tid]; s += v; q += v * v; }
            __stcg(&d_sum1[tid * NCTA + cta], s);
            __stcg(&d_ssq1[tid * NCTA + cta], q);
        }
        gridbar(genc);

        // ============ Phase C : output (CTAs 0..63, one batch each) ============
        if (cta < 64) {
            const int b = cta;
            if (tid < 128) {
                LR[tid]       = __ldcg(&d_sum1[b * NCTA + tid]);
                LR[128 + tid] = __ldcg(&d_ssq1[b * NCTA + tid]);
            }
            float* ONr = smemf;          // 1024 (reuse; safe after gridbar)
            float* FC  = smemf + 1024;   // 512
            __syncthreads();
            if (tid < 32) {
                float s = LR[tid] + LR[tid + 32] + LR[tid + 64] + LR[tid + 96];
                float q = LR[128 + tid] + LR[160 + tid] + LR[192 + tid] + LR[224 + tid];
                #pragma unroll
                for (int o = 16; o; o >>= 1) {
                    s += __shfl_xor_sync(0xffffffffu, s, o);
                    q += __shfl_xor_sync(0xffffffffu, q, o);
                }
                if (tid == 0) {
                    float mu = s * (1.f / 1024.f);
                    float var = q * (1.f / 1024.f) - mu * mu;
                    CMU[0] = mu; CMU[1] = rsqrtf(var + 1e-3f);
                }
            }
            ONr[tid]       = __ldcg(&d_h1T[b * UNITS + tid]);          // coalesced
            ONr[512 + tid] = __ldcg(&d_h1T[b * UNITS + 512 + tid]);
            __syncthreads();
            {
                const int cls = tid & 15, seg = tid >> 4;   // 32 segs x 32 units
                float p = 0.f;
                #pragma unroll 8
                for (int u = seg * 32; u < seg * 32 + 32; u++)
                    p += ONr[u] * __ldg(&d_Wfcg[u * 16 + cls]);
                FC[seg * 16 + cls] = p;
            }
            __syncthreads();
            if (tid < 16) {
                float zraw = 0.f;
                #pragma unroll
                for (int s2 = 0; s2 < 32; s2++) zraw += FC[s2 * 16 + tid];
                LG[tid] = CMU[1] * zraw - CMU[0] * CMU[1] * __ldg(&d_csf[tid]) + __ldg(&d_bfcp[tid]);
            }
            __syncthreads();
            if (tid < 16) {
                float m = -1e30f;
                #pragma unroll
                for (int i = 0; i < 16; i++) m = fmaxf(m, LG[i]);
                float s = 0.f;
                #pragma unroll
                for (int i = 0; i < 16; i++) s += expf(LG[i] - m);
                out[(size_t)b * TSTEPS * NCLS + (size_t)t * NCLS + tid] = expf(LG[tid] - m) / s;
            }
            __syncthreads();
        }
    }
}

// ------------------------------ launcher ------------------------------
extern "C" void kernel_launch(void* const* d_in, const int* in_sizes, int n_in,
                              void* d_out, int out_size) {
    const float* in  = (const float*)d_in[0];
    const float* W0  = (const float*)d_in[1];
    const float* U0  = (const float*)d_in[2];
    const float* b0  = (const float*)d_in[3];
    const float* g0  = (const float*)d_in[4];
    const float* be0 = (const float*)d_in[5];
    const float* W1  = (const float*)d_in[6];
    const float* U1  = (const float*)d_in[7];
    const float* b1  = (const float*)d_in[8];
    const float* g1  = (const float*)d_in[9];
    const float* be1 = (const float*)d_in[10];
    const float* Wfc = (const float*)d_in[11];
    const float* bfc = (const float*)d_in[12];
    float* out = (float*)d_out;

    static int smem_attr_set = 0;
    if (!smem_attr_set) {
        cudaFuncSetAttribute(lstm_persist, cudaFuncAttributeMaxDynamicSharedMemorySize, 149504);
        smem_attr_set = 1;
    }

    prep_kernel<<<8192, 256>>>(in, W0, U0, b0, g0, be0, W1, U1, b1, g1, be1, Wfc, bfc);
    lstm_persist<<<NCTA, NTHR, 149504>>>(in, out);
}